// round 9
// baseline (speedup 1.0000x reference)
#include <cuda_runtime.h>
#include <math.h>

#define NN_  262144
#define B_   256
#define N_   1024
#define DEG_ 8
#define E_   (NN_*DEG_)
#define D_   128

typedef unsigned long long ull;

// ------------------------- scratch -------------------------
__device__ float g_X[NN_*D_];
__device__ float g_AGG[NN_*D_];
__device__ float g_score[NN_];
__device__ float g_gate[NN_];
__device__ int   g_nm[NN_];
__device__ int   g_off[NN_];
__device__ int   g_deg[NN_];
__device__ int   g_csr[E_];
__device__ int   g_rows[2][NN_];   // kept-row lists (ping-pong)
__device__ float g_H[B_*2*D_];

// ------------------------- f32x2 helpers -------------------------
__device__ __forceinline__ ull bcast2(float a){ ull r; asm("mov.b64 %0, {%1,%1};" : "=l"(r) : "f"(a)); return r; }
__device__ __forceinline__ float2 unpk(ull v){ float2 f; asm("mov.b64 {%0,%1}, %2;" : "=f"(f.x),"=f"(f.y) : "l"(v)); return f; }
__device__ __forceinline__ void fma2(ull &d, ull a, ull b){ asm("fma.rn.f32x2 %0, %1, %2, %0;" : "+l"(d) : "l"(a),"l"(b)); }

// ------------------------- init -------------------------
__global__ void k_init(const int* __restrict__ ids, const float* __restrict__ emb){
    long tid0 = (long)blockIdx.x*blockDim.x + threadIdx.x;
    long stride = (long)gridDim.x*blockDim.x;
    const float4* emb4 = (const float4*)emb;
    float4* X4 = (float4*)g_X;
    for (long v = tid0; v < (long)NN_*32; v += stride){
        int n = (int)(v >> 5), c = (int)(v & 31);
        int id = ids[n];
        X4[v] = emb4[(long)id*32 + c];
    }
    for (long i = tid0; i < NN_; i += stride) g_nm[i] = 1;
    for (long i = tid0; i < B_*2*D_; i += stride) g_H[i] = 0.f;
}

// ------------------------- CSR build: one kernel, per-graph in shared -------------------------
__global__ void __launch_bounds__(1024) k_csr(const int* __restrict__ ei){
    __shared__ int scnt[1024];
    __shared__ int soff[1024];
    int b = blockIdx.x, t = threadIdx.x;
    scnt[t] = 0;
    __syncthreads();
    int ebase = b * (N_*DEG_);
    int dl[8];
    #pragma unroll
    for (int i = 0; i < 8; i++){
        dl[i] = ei[E_ + ebase + t + i*1024] - b*N_;
        atomicAdd(&scnt[dl[i]], 1);
    }
    __syncthreads();
    int d = scnt[t];
    soff[t] = d;
    __syncthreads();
    for (int o = 1; o < 1024; o <<= 1){
        int v = (t >= o) ? soff[t-o] : 0;
        __syncthreads();
        soff[t] += v;
        __syncthreads();
    }
    int excl = soff[t] - d;
    g_off[b*N_ + t] = ebase + excl;
    g_deg[b*N_ + t] = d;
    __syncthreads();
    scnt[t] = excl;          // reuse as fill cursor
    __syncthreads();
    #pragma unroll
    for (int i = 0; i < 8; i++){
        int pos = atomicAdd(&scnt[dl[i]], 1);
        g_csr[ebase + pos] = ei[ebase + t + i*1024];
    }
}

// ------------------------- mean aggregation (gather, kept rows only) -------------------------
// Dropped-source rows of X are exactly zero, so the sum needs no mask; only the
// count does. Source indices prefetched 8 at a time -> MLP ~8.
__global__ void __launch_bounds__(256) k_agg(int sel, int prevK){
    int w = (blockIdx.x*256 + threadIdx.x) >> 5;
    int lane = threadIdx.x & 31;
    int g;
    if (sel < 0) g = w;
    else { int b = w / prevK; g = g_rows[sel][b*N_ + (w - b*prevK)]; }
    float4 acc = make_float4(0.f,0.f,0.f,0.f);
    int cnt = 0;
    int off = g_off[g], dcnt = g_deg[g];
    const float4* X4 = (const float4*)g_X;
    for (int base = 0; base < dcnt; base += 8){
        int m = dcnt - base; if (m > 8) m = 8;
        int ss[8];
        #pragma unroll
        for (int j = 0; j < 8; j++) ss[j] = (j < m) ? g_csr[off + base + j] : 0;
        #pragma unroll
        for (int j = 0; j < 8; j++) if (j < m){
            float4 v = X4[(long)ss[j]*32 + lane];
            acc.x += v.x; acc.y += v.y; acc.z += v.z; acc.w += v.w;
            cnt += g_nm[ss[j]];
        }
    }
    float inv = 1.0f / (float)(cnt > 1 ? cnt : 1);
    acc.x *= inv; acc.y *= inv; acc.z *= inv; acc.w *= inv;
    ((float4*)g_AGG)[(long)g*32 + lane] = acc;
}

// ------------------------- fused GEMM + score -------------------------
// X[g] = relu(AGG[g]@Wl + bl + X[g]@Wr) for kept rows g; score[g] = X[g].p
// Block: 128 thr = 4 warps x 32 rows (row-pairs packed in f32x2 accumulators).
// Shared holds A,X transposed [k][r] with an even-XOR swizzle (conflict-free
// stores, broadcast reads, row-pairs stay adjacent).
#define SWA(k, r) (((k)<<5) + ((r) ^ ((k)&30)))

__global__ void __launch_bounds__(128) k_gemm(const float* __restrict__ Wl,
                                              const float* __restrict__ blp,
                                              const float* __restrict__ Wr,
                                              const float* __restrict__ p,
                                              int sel, int prevK){
    __shared__ float sA[128*32];
    __shared__ float sXm[128*32];
    __shared__ int sRow[32];
    int t = threadIdx.x;
    int rb = blockIdx.x * 32;
    if (t < 32){
        int j = rb + t, g;
        if (sel < 0) g = j;
        else { int b = j / prevK; g = g_rows[sel][b*N_ + (j - b*prevK)]; }
        sRow[t] = g;
    }
    __syncthreads();
    {   // load + transpose: warp w -> rows 8w..8w+7; lane = (rquad, c8)
        int w = t >> 5, lane = t & 31;
        int rq = lane >> 3, c8 = lane & 7;
        const float4* A4 = (const float4*)g_AGG;
        const float4* X4 = (const float4*)g_X;
        #pragma unroll
        for (int half = 0; half < 2; half++){
            int r = w*8 + half*4 + rq;
            long gr = (long)sRow[r]*32;
            #pragma unroll
            for (int cg = 0; cg < 4; cg++){
                int ch = c8 + cg*8;
                float4 a = A4[gr + ch];
                float4 x = X4[gr + ch];
                int k0 = ch*4;
                sA [SWA(k0+0,r)] = a.x; sA [SWA(k0+1,r)] = a.y;
                sA [SWA(k0+2,r)] = a.z; sA [SWA(k0+3,r)] = a.w;
                sXm[SWA(k0+0,r)] = x.x; sXm[SWA(k0+1,r)] = x.y;
                sXm[SWA(k0+2,r)] = x.z; sXm[SWA(k0+3,r)] = x.w;
            }
        }
    }
    __syncthreads();

    int q = t & 31, h = t >> 5;
    int r0 = h * 8;
    const float4* Wl4 = (const float4*)Wl;
    const float4* Wr4 = (const float4*)Wr;
    float4 bl4 = ((const float4*)blp)[q];
    ull acc[4][4];
    {
        ull b0 = bcast2(bl4.x), b1 = bcast2(bl4.y), b2 = bcast2(bl4.z), b3 = bcast2(bl4.w);
        #pragma unroll
        for (int rr = 0; rr < 4; rr++){ acc[rr][0]=b0; acc[rr][1]=b1; acc[rr][2]=b2; acc[rr][3]=b3; }
    }

    #pragma unroll 2
    for (int k = 0; k < 128; k++){
        float4 wl = Wl4[k*32 + q];
        float4 wr = Wr4[k*32 + q];
        ull wl0=bcast2(wl.x), wl1=bcast2(wl.y), wl2=bcast2(wl.z), wl3=bcast2(wl.w);
        ull wr0=bcast2(wr.x), wr1=bcast2(wr.y), wr2=bcast2(wr.z), wr3=bcast2(wr.w);
        #pragma unroll
        for (int rr = 0; rr < 4; rr++){
            ull a2 = *(const ull*)&sA [SWA(k, r0 + 2*rr)];
            ull x2 = *(const ull*)&sXm[SWA(k, r0 + 2*rr)];
            fma2(acc[rr][0], a2, wl0); fma2(acc[rr][0], x2, wr0);
            fma2(acc[rr][1], a2, wl1); fma2(acc[rr][1], x2, wr1);
            fma2(acc[rr][2], a2, wl2); fma2(acc[rr][2], x2, wr2);
            fma2(acc[rr][3], a2, wl3); fma2(acc[rr][3], x2, wr3);
        }
    }

    float4 p4 = ((const float4*)p)[q];
    float4* Xo = (float4*)g_X;
    #pragma unroll
    for (int rr = 0; rr < 4; rr++){
        float2 c0 = unpk(acc[rr][0]), c1 = unpk(acc[rr][1]);
        float2 c2 = unpk(acc[rr][2]), c3 = unpk(acc[rr][3]);
        float4 o0 = make_float4(fmaxf(c0.x,0.f), fmaxf(c1.x,0.f), fmaxf(c2.x,0.f), fmaxf(c3.x,0.f));
        float4 o1 = make_float4(fmaxf(c0.y,0.f), fmaxf(c1.y,0.f), fmaxf(c2.y,0.f), fmaxf(c3.y,0.f));
        int ga = sRow[r0 + 2*rr], gb = sRow[r0 + 2*rr + 1];
        Xo[(long)ga*32 + q] = o0;
        Xo[(long)gb*32 + q] = o1;
        float s0 = o0.x*p4.x + o0.y*p4.y + o0.z*p4.z + o0.w*p4.w;
        float s1 = o1.x*p4.x + o1.y*p4.y + o1.z*p4.z + o1.w*p4.w;
        #pragma unroll
        for (int o = 16; o > 0; o >>= 1){
            s0 += __shfl_xor_sync(0xffffffffu, s0, o);
            s1 += __shfl_xor_sync(0xffffffffu, s1, o);
        }
        if (q == 0){ g_score[ga] = s0; g_score[gb] = s1; }
    }
}

// ------------------------- per-graph topk (sort-only; scores precomputed) -------------------------
__device__ __forceinline__ unsigned ordu(float f){
    unsigned u = __float_as_uint(f);
    return (u >> 31) ? ~u : (u | 0x80000000u);
}

__global__ void __launch_bounds__(1024) k_topk(const float* __restrict__ p, int K, int buf){
    __shared__ float sp[128];
    __shared__ ull skey[1024];
    __shared__ int skeep[1024];
    __shared__ float snorm;
    int b = blockIdx.x, t = threadIdx.x;
    if (t < 128) sp[t] = p[t];
    __syncthreads();
    if (t == 0){
        float s = 0.f;
        for (int i = 0; i < 128; i++) s += sp[i]*sp[i];
        snorm = rsqrtf(s);
    }
    __syncthreads();
    int g = b*N_ + t;
    int oldnm = g_nm[g];
    float sc = g_score[g] * snorm;
    float skk = oldnm ? sc : -INFINITY;
    skey[t] = (((ull)(~ordu(skk))) << 32) | (unsigned)t;
    skeep[t] = 0;

    for (unsigned kk = 2; kk <= 1024; kk <<= 1){
        for (unsigned j = kk >> 1; j > 0; j >>= 1){
            __syncthreads();
            unsigned ixj = t ^ j;
            if (ixj > (unsigned)t){
                ull a = skey[t], bb = skey[ixj];
                bool asc = ((t & kk) == 0);
                bool sw = asc ? (a > bb) : (a < bb);
                if (sw){ skey[t] = bb; skey[ixj] = a; }
            }
        }
    }
    __syncthreads();
    if (t < K){
        int idx = (int)(skey[t] & 0xffffffffu);
        skeep[idx] = 1;
        g_rows[buf][b*N_ + t] = b*N_ + idx;
    }
    __syncthreads();
    int keep = skeep[t];
    g_nm[g] = keep;
    g_gate[g] = keep ? tanhf(sc) : 0.f;
}

// ------------------------- fused scale + readout (prev-kept rows only) -------------------------
__global__ void __launch_bounds__(512) k_sr(int sel, int prevK, float Kinv){
    __shared__ float4 ssum[16][32];
    __shared__ float4 smax[16][32];
    int b = blockIdx.x, t = threadIdx.x;
    int grp = t >> 5, lane = t & 31;
    float4 sum = make_float4(0.f,0.f,0.f,0.f);
    float4 mx  = make_float4(-INFINITY,-INFINITY,-INFINITY,-INFINITY);
    float4* X4 = (float4*)g_X;
    for (int j = grp; j < prevK; j += 16){
        int g = (sel < 0) ? b*N_ + j : g_rows[sel][b*N_ + j];
        float gt = g_gate[g];
        float4 v = X4[(long)g*32 + lane];
        v.x *= gt; v.y *= gt; v.z *= gt; v.w *= gt;
        X4[(long)g*32 + lane] = v;
        if (g_nm[g]){
            sum.x += v.x; sum.y += v.y; sum.z += v.z; sum.w += v.w;
            mx.x = fmaxf(mx.x, v.x); mx.y = fmaxf(mx.y, v.y);
            mx.z = fmaxf(mx.z, v.z); mx.w = fmaxf(mx.w, v.w);
        }
    }
    ssum[grp][lane] = sum; smax[grp][lane] = mx;
    __syncthreads();
    if (t < 32){
        float4 S = make_float4(0.f,0.f,0.f,0.f);
        float4 M = make_float4(-INFINITY,-INFINITY,-INFINITY,-INFINITY);
        #pragma unroll
        for (int gg = 0; gg < 16; gg++){
            float4 s = ssum[gg][t], m = smax[gg][t];
            S.x += s.x; S.y += s.y; S.z += s.z; S.w += s.w;
            M.x = fmaxf(M.x, m.x); M.y = fmaxf(M.y, m.y);
            M.z = fmaxf(M.z, m.z); M.w = fmaxf(M.w, m.w);
        }
        g_H[b*256 + 4*t+0] += M.x; g_H[b*256 + 4*t+1] += M.y;
        g_H[b*256 + 4*t+2] += M.z; g_H[b*256 + 4*t+3] += M.w;
        g_H[b*256 + 128 + 4*t+0] += S.x*Kinv; g_H[b*256 + 128 + 4*t+1] += S.y*Kinv;
        g_H[b*256 + 128 + 4*t+2] += S.z*Kinv; g_H[b*256 + 128 + 4*t+3] += S.w*Kinv;
    }
}

// ------------------------- final MLP -------------------------
__global__ void __launch_bounds__(128) k_mlp(const float* __restrict__ W1, const float* __restrict__ b1,
                                             const float* __restrict__ W2, const float* __restrict__ b2,
                                             const float* __restrict__ W3, const float* __restrict__ b3,
                                             float* __restrict__ out){
    __shared__ float h[256], h1[128], h2[64];
    int b = blockIdx.x, t = threadIdx.x;
    h[t] = g_H[b*256 + t];
    h[t + 128] = g_H[b*256 + 128 + t];
    __syncthreads();
    float a = b1[t];
    #pragma unroll 8
    for (int k = 0; k < 256; k++) a += h[k] * W1[k*128 + t];
    h1[t] = fmaxf(a, 0.f);
    __syncthreads();
    if (t < 64){
        float a2 = b2[t];
        #pragma unroll 8
        for (int k = 0; k < 128; k++) a2 += h1[k] * W2[k*64 + t];
        h2[t] = fmaxf(a2, 0.f);
    }
    __syncthreads();
    if (t == 0){
        float z = b3[0];
        for (int k = 0; k < 64; k++) z += h2[k] * W3[k];
        out[b] = 1.f / (1.f + expf(-z));
    }
}

// ------------------------- launch -------------------------
extern "C" void kernel_launch(void* const* d_in, const int* in_sizes, int n_in,
                              void* d_out, int out_size){
    const int*   x_ids = (const int*)d_in[0];
    const int*   ei    = (const int*)d_in[1];
    const float* emb   = (const float*)d_in[3];
    const float* Wl[3] = {(const float*)d_in[4],  (const float*)d_in[8],  (const float*)d_in[12]};
    const float* bl[3] = {(const float*)d_in[5],  (const float*)d_in[9],  (const float*)d_in[13]};
    const float* Wr[3] = {(const float*)d_in[6],  (const float*)d_in[10], (const float*)d_in[14]};
    const float* pp[3] = {(const float*)d_in[7],  (const float*)d_in[11], (const float*)d_in[15]};
    const int pk[3] = {1024, 820, 656};   // rows alive entering layer l (per graph)
    const int Ks[3] = {820, 656, 525};    // rows kept by layer l's topk

    k_init<<<8192, 256>>>(x_ids, emb);
    k_csr<<<B_, 1024>>>(ei);

    for (int l = 0; l < 3; l++){
        int sel = (l == 0) ? -1 : ((l-1) & 1);
        k_agg <<<32*pk[l], 256>>>(sel, pk[l]);
        k_gemm<<<8*pk[l], 128>>>(Wl[l], bl[l], Wr[l], pp[l], sel, pk[l]);
        k_topk<<<B_, 1024>>>(pp[l], Ks[l], l & 1);
        k_sr  <<<B_, 512>>>(sel, pk[l], 1.0f / (float)Ks[l]);
    }
    k_mlp<<<B_, 128>>>((const float*)d_in[16], (const float*)d_in[17],
                       (const float*)d_in[18], (const float*)d_in[19],
                       (const float*)d_in[20], (const float*)d_in[21],
                       (float*)d_out);
}

// round 10
// speedup vs baseline: 1.0087x; 1.0087x over previous
#include <cuda_runtime.h>
#include <math.h>

#define NN_  262144
#define B_   256
#define N_   1024
#define DEG_ 8
#define E_   (NN_*DEG_)
#define D_   128

typedef unsigned long long ull;

// ------------------------- scratch -------------------------
__device__ float g_X[NN_*D_];
__device__ float g_AGG[NN_*D_];
__device__ float g_score[NN_];
__device__ float g_gate[NN_];
__device__ int   g_nm[NN_];
__device__ int   g_off[NN_];
__device__ int   g_deg[NN_];
__device__ int   g_csr[E_];
__device__ int   g_rows[2][NN_];   // kept-row lists (ping-pong)
__device__ float g_H[B_*2*D_];

// ------------------------- f32x2 helpers -------------------------
__device__ __forceinline__ ull bcast2(float a){ ull r; asm("mov.b64 %0, {%1,%1};" : "=l"(r) : "f"(a)); return r; }
__device__ __forceinline__ float2 unpk(ull v){ float2 f; asm("mov.b64 {%0,%1}, %2;" : "=f"(f.x),"=f"(f.y) : "l"(v)); return f; }
__device__ __forceinline__ void fma2(ull &d, ull a, ull b){ asm("fma.rn.f32x2 %0, %1, %2, %0;" : "+l"(d) : "l"(a),"l"(b)); }

// ------------------------- init -------------------------
__global__ void k_init(const int* __restrict__ ids, const float* __restrict__ emb){
    long tid0 = (long)blockIdx.x*blockDim.x + threadIdx.x;
    long stride = (long)gridDim.x*blockDim.x;
    const float4* emb4 = (const float4*)emb;
    float4* X4 = (float4*)g_X;
    for (long v = tid0; v < (long)NN_*32; v += stride){
        int n = (int)(v >> 5), c = (int)(v & 31);
        int id = ids[n];
        X4[v] = emb4[(long)id*32 + c];
    }
    for (long i = tid0; i < NN_; i += stride) g_nm[i] = 1;
    for (long i = tid0; i < B_*2*D_; i += stride) g_H[i] = 0.f;
}

// ------------------------- CSR build: one kernel, per-graph in shared -------------------------
__global__ void __launch_bounds__(1024) k_csr(const int* __restrict__ ei){
    __shared__ int scnt[1024];
    __shared__ int soff[1024];
    int b = blockIdx.x, t = threadIdx.x;
    scnt[t] = 0;
    __syncthreads();
    int ebase = b * (N_*DEG_);
    int dl[8];
    #pragma unroll
    for (int i = 0; i < 8; i++){
        dl[i] = ei[E_ + ebase + t + i*1024] - b*N_;
        atomicAdd(&scnt[dl[i]], 1);
    }
    __syncthreads();
    int d = scnt[t];
    soff[t] = d;
    __syncthreads();
    for (int o = 1; o < 1024; o <<= 1){
        int v = (t >= o) ? soff[t-o] : 0;
        __syncthreads();
        soff[t] += v;
        __syncthreads();
    }
    int excl = soff[t] - d;
    g_off[b*N_ + t] = ebase + excl;
    g_deg[b*N_ + t] = d;
    __syncthreads();
    scnt[t] = excl;          // reuse as fill cursor
    __syncthreads();
    #pragma unroll
    for (int i = 0; i < 8; i++){
        int pos = atomicAdd(&scnt[dl[i]], 1);
        g_csr[ebase + pos] = ei[ebase + t + i*1024];
    }
}

// ------------------------- mean aggregation (gather, kept rows only) -------------------------
// Dropped-source rows of X are exactly zero, so the sum needs no mask; only the
// count does. Source indices prefetched 8 at a time -> MLP ~8.
__global__ void __launch_bounds__(256) k_agg(int sel, int prevK){
    int w = (blockIdx.x*256 + threadIdx.x) >> 5;
    int lane = threadIdx.x & 31;
    int g;
    if (sel < 0) g = w;
    else { int b = w / prevK; g = g_rows[sel][b*N_ + (w - b*prevK)]; }
    float4 acc = make_float4(0.f,0.f,0.f,0.f);
    int cnt = 0;
    int off = g_off[g], dcnt = g_deg[g];
    const float4* X4 = (const float4*)g_X;
    for (int base = 0; base < dcnt; base += 8){
        int m = dcnt - base; if (m > 8) m = 8;
        int ss[8];
        #pragma unroll
        for (int j = 0; j < 8; j++) ss[j] = (j < m) ? g_csr[off + base + j] : 0;
        #pragma unroll
        for (int j = 0; j < 8; j++) if (j < m){
            float4 v = X4[(long)ss[j]*32 + lane];
            acc.x += v.x; acc.y += v.y; acc.z += v.z; acc.w += v.w;
            cnt += g_nm[ss[j]];
        }
    }
    float inv = 1.0f / (float)(cnt > 1 ? cnt : 1);
    acc.x *= inv; acc.y *= inv; acc.z *= inv; acc.w *= inv;
    ((float4*)g_AGG)[(long)g*32 + lane] = acc;
}

// ------------------------- fused GEMM + score -------------------------
// X[g] = relu(AGG[g]@Wl + bl + X[g]@Wr) for kept rows g; score[g] = X[g].p
// Block: 128 thr = 4 warps x 32 rows (row-pairs packed in f32x2 accumulators).
// Shared holds A,X transposed [k][r] with an even-XOR swizzle (conflict-free
// stores, broadcast reads, row-pairs stay adjacent).
#define SWA(k, r) (((k)<<5) + ((r) ^ ((k)&30)))

__global__ void __launch_bounds__(128) k_gemm(const float* __restrict__ Wl,
                                              const float* __restrict__ blp,
                                              const float* __restrict__ Wr,
                                              const float* __restrict__ p,
                                              int sel, int prevK){
    __shared__ float sA[128*32];
    __shared__ float sXm[128*32];
    __shared__ int sRow[32];
    int t = threadIdx.x;
    int rb = blockIdx.x * 32;
    if (t < 32){
        int j = rb + t, g;
        if (sel < 0) g = j;
        else { int b = j / prevK; g = g_rows[sel][b*N_ + (j - b*prevK)]; }
        sRow[t] = g;
    }
    __syncthreads();
    {   // load + transpose: warp w -> rows 8w..8w+7; lane = (rquad, c8)
        int w = t >> 5, lane = t & 31;
        int rq = lane >> 3, c8 = lane & 7;
        const float4* A4 = (const float4*)g_AGG;
        const float4* X4 = (const float4*)g_X;
        #pragma unroll
        for (int half = 0; half < 2; half++){
            int r = w*8 + half*4 + rq;
            long gr = (long)sRow[r]*32;
            #pragma unroll
            for (int cg = 0; cg < 4; cg++){
                int ch = c8 + cg*8;
                float4 a = A4[gr + ch];
                float4 x = X4[gr + ch];
                int k0 = ch*4;
                sA [SWA(k0+0,r)] = a.x; sA [SWA(k0+1,r)] = a.y;
                sA [SWA(k0+2,r)] = a.z; sA [SWA(k0+3,r)] = a.w;
                sXm[SWA(k0+0,r)] = x.x; sXm[SWA(k0+1,r)] = x.y;
                sXm[SWA(k0+2,r)] = x.z; sXm[SWA(k0+3,r)] = x.w;
            }
        }
    }
    __syncthreads();

    int q = t & 31, h = t >> 5;
    int r0 = h * 8;
    const float4* Wl4 = (const float4*)Wl;
    const float4* Wr4 = (const float4*)Wr;
    float4 bl4 = ((const float4*)blp)[q];
    ull acc[4][4];
    {
        ull b0 = bcast2(bl4.x), b1 = bcast2(bl4.y), b2 = bcast2(bl4.z), b3 = bcast2(bl4.w);
        #pragma unroll
        for (int rr = 0; rr < 4; rr++){ acc[rr][0]=b0; acc[rr][1]=b1; acc[rr][2]=b2; acc[rr][3]=b3; }
    }

    #pragma unroll 2
    for (int k = 0; k < 128; k++){
        float4 wl = Wl4[k*32 + q];
        float4 wr = Wr4[k*32 + q];
        ull wl0=bcast2(wl.x), wl1=bcast2(wl.y), wl2=bcast2(wl.z), wl3=bcast2(wl.w);
        ull wr0=bcast2(wr.x), wr1=bcast2(wr.y), wr2=bcast2(wr.z), wr3=bcast2(wr.w);
        #pragma unroll
        for (int rr = 0; rr < 4; rr++){
            ull a2 = *(const ull*)&sA [SWA(k, r0 + 2*rr)];
            ull x2 = *(const ull*)&sXm[SWA(k, r0 + 2*rr)];
            fma2(acc[rr][0], a2, wl0); fma2(acc[rr][0], x2, wr0);
            fma2(acc[rr][1], a2, wl1); fma2(acc[rr][1], x2, wr1);
            fma2(acc[rr][2], a2, wl2); fma2(acc[rr][2], x2, wr2);
            fma2(acc[rr][3], a2, wl3); fma2(acc[rr][3], x2, wr3);
        }
    }

    float4 p4 = ((const float4*)p)[q];
    float4* Xo = (float4*)g_X;
    #pragma unroll
    for (int rr = 0; rr < 4; rr++){
        float2 c0 = unpk(acc[rr][0]), c1 = unpk(acc[rr][1]);
        float2 c2 = unpk(acc[rr][2]), c3 = unpk(acc[rr][3]);
        float4 o0 = make_float4(fmaxf(c0.x,0.f), fmaxf(c1.x,0.f), fmaxf(c2.x,0.f), fmaxf(c3.x,0.f));
        float4 o1 = make_float4(fmaxf(c0.y,0.f), fmaxf(c1.y,0.f), fmaxf(c2.y,0.f), fmaxf(c3.y,0.f));
        int ga = sRow[r0 + 2*rr], gb = sRow[r0 + 2*rr + 1];
        Xo[(long)ga*32 + q] = o0;
        Xo[(long)gb*32 + q] = o1;
        float s0 = o0.x*p4.x + o0.y*p4.y + o0.z*p4.z + o0.w*p4.w;
        float s1 = o1.x*p4.x + o1.y*p4.y + o1.z*p4.z + o1.w*p4.w;
        #pragma unroll
        for (int o = 16; o > 0; o >>= 1){
            s0 += __shfl_xor_sync(0xffffffffu, s0, o);
            s1 += __shfl_xor_sync(0xffffffffu, s1, o);
        }
        if (q == 0){ g_score[ga] = s0; g_score[gb] = s1; }
    }
}

// ------------------------- per-graph topk (sort-only; scores precomputed) -------------------------
__device__ __forceinline__ unsigned ordu(float f){
    unsigned u = __float_as_uint(f);
    return (u >> 31) ? ~u : (u | 0x80000000u);
}

__global__ void __launch_bounds__(1024) k_topk(const float* __restrict__ p, int K, int buf){
    __shared__ float sp[128];
    __shared__ ull skey[1024];
    __shared__ int skeep[1024];
    __shared__ float snorm;
    int b = blockIdx.x, t = threadIdx.x;
    if (t < 128) sp[t] = p[t];
    __syncthreads();
    if (t == 0){
        float s = 0.f;
        for (int i = 0; i < 128; i++) s += sp[i]*sp[i];
        snorm = rsqrtf(s);
    }
    __syncthreads();
    int g = b*N_ + t;
    int oldnm = g_nm[g];
    float sc = g_score[g] * snorm;
    float skk = oldnm ? sc : -INFINITY;
    skey[t] = (((ull)(~ordu(skk))) << 32) | (unsigned)t;
    skeep[t] = 0;

    for (unsigned kk = 2; kk <= 1024; kk <<= 1){
        for (unsigned j = kk >> 1; j > 0; j >>= 1){
            __syncthreads();
            unsigned ixj = t ^ j;
            if (ixj > (unsigned)t){
                ull a = skey[t], bb = skey[ixj];
                bool asc = ((t & kk) == 0);
                bool sw = asc ? (a > bb) : (a < bb);
                if (sw){ skey[t] = bb; skey[ixj] = a; }
            }
        }
    }
    __syncthreads();
    if (t < K){
        int idx = (int)(skey[t] & 0xffffffffu);
        skeep[idx] = 1;
        g_rows[buf][b*N_ + t] = b*N_ + idx;
    }
    __syncthreads();
    int keep = skeep[t];
    g_nm[g] = keep;
    g_gate[g] = keep ? tanhf(sc) : 0.f;
}

// ------------------------- fused scale + readout (prev-kept rows only) -------------------------
__global__ void __launch_bounds__(512) k_sr(int sel, int prevK, float Kinv){
    __shared__ float4 ssum[16][32];
    __shared__ float4 smax[16][32];
    int b = blockIdx.x, t = threadIdx.x;
    int grp = t >> 5, lane = t & 31;
    float4 sum = make_float4(0.f,0.f,0.f,0.f);
    float4 mx  = make_float4(-INFINITY,-INFINITY,-INFINITY,-INFINITY);
    float4* X4 = (float4*)g_X;
    for (int j = grp; j < prevK; j += 16){
        int g = (sel < 0) ? b*N_ + j : g_rows[sel][b*N_ + j];
        float gt = g_gate[g];
        float4 v = X4[(long)g*32 + lane];
        v.x *= gt; v.y *= gt; v.z *= gt; v.w *= gt;
        X4[(long)g*32 + lane] = v;
        if (g_nm[g]){
            sum.x += v.x; sum.y += v.y; sum.z += v.z; sum.w += v.w;
            mx.x = fmaxf(mx.x, v.x); mx.y = fmaxf(mx.y, v.y);
            mx.z = fmaxf(mx.z, v.z); mx.w = fmaxf(mx.w, v.w);
        }
    }
    ssum[grp][lane] = sum; smax[grp][lane] = mx;
    __syncthreads();
    if (t < 32){
        float4 S = make_float4(0.f,0.f,0.f,0.f);
        float4 M = make_float4(-INFINITY,-INFINITY,-INFINITY,-INFINITY);
        #pragma unroll
        for (int gg = 0; gg < 16; gg++){
            float4 s = ssum[gg][t], m = smax[gg][t];
            S.x += s.x; S.y += s.y; S.z += s.z; S.w += s.w;
            M.x = fmaxf(M.x, m.x); M.y = fmaxf(M.y, m.y);
            M.z = fmaxf(M.z, m.z); M.w = fmaxf(M.w, m.w);
        }
        g_H[b*256 + 4*t+0] += M.x; g_H[b*256 + 4*t+1] += M.y;
        g_H[b*256 + 4*t+2] += M.z; g_H[b*256 + 4*t+3] += M.w;
        g_H[b*256 + 128 + 4*t+0] += S.x*Kinv; g_H[b*256 + 128 + 4*t+1] += S.y*Kinv;
        g_H[b*256 + 128 + 4*t+2] += S.z*Kinv; g_H[b*256 + 128 + 4*t+3] += S.w*Kinv;
    }
}

// ------------------------- final MLP -------------------------
__global__ void __launch_bounds__(128) k_mlp(const float* __restrict__ W1, const float* __restrict__ b1,
                                             const float* __restrict__ W2, const float* __restrict__ b2,
                                             const float* __restrict__ W3, const float* __restrict__ b3,
                                             float* __restrict__ out){
    __shared__ float h[256], h1[128], h2[64];
    int b = blockIdx.x, t = threadIdx.x;
    h[t] = g_H[b*256 + t];
    h[t + 128] = g_H[b*256 + 128 + t];
    __syncthreads();
    float a = b1[t];
    #pragma unroll 8
    for (int k = 0; k < 256; k++) a += h[k] * W1[k*128 + t];
    h1[t] = fmaxf(a, 0.f);
    __syncthreads();
    if (t < 64){
        float a2 = b2[t];
        #pragma unroll 8
        for (int k = 0; k < 128; k++) a2 += h1[k] * W2[k*64 + t];
        h2[t] = fmaxf(a2, 0.f);
    }
    __syncthreads();
    if (t == 0){
        float z = b3[0];
        for (int k = 0; k < 64; k++) z += h2[k] * W3[k];
        out[b] = 1.f / (1.f + expf(-z));
    }
}

// ------------------------- launch -------------------------
extern "C" void kernel_launch(void* const* d_in, const int* in_sizes, int n_in,
                              void* d_out, int out_size){
    const int*   x_ids = (const int*)d_in[0];
    const int*   ei    = (const int*)d_in[1];
    const float* emb   = (const float*)d_in[3];
    const float* Wl[3] = {(const float*)d_in[4],  (const float*)d_in[8],  (const float*)d_in[12]};
    const float* bl[3] = {(const float*)d_in[5],  (const float*)d_in[9],  (const float*)d_in[13]};
    const float* Wr[3] = {(const float*)d_in[6],  (const float*)d_in[10], (const float*)d_in[14]};
    const float* pp[3] = {(const float*)d_in[7],  (const float*)d_in[11], (const float*)d_in[15]};
    const int pk[3] = {1024, 820, 656};   // rows alive entering layer l (per graph)
    const int Ks[3] = {820, 656, 525};    // rows kept by layer l's topk

    k_init<<<8192, 256>>>(x_ids, emb);
    k_csr<<<B_, 1024>>>(ei);

    for (int l = 0; l < 3; l++){
        int sel = (l == 0) ? -1 : ((l-1) & 1);
        k_agg <<<32*pk[l], 256>>>(sel, pk[l]);
        k_gemm<<<8*pk[l], 128>>>(Wl[l], bl[l], Wr[l], pp[l], sel, pk[l]);
        k_topk<<<B_, 1024>>>(pp[l], Ks[l], l & 1);
        k_sr  <<<B_, 512>>>(sel, pk[l], 1.0f / (float)Ks[l]);
    }
    k_mlp<<<B_, 128>>>((const float*)d_in[16], (const float*)d_in[17],
                       (const float*)d_in[18], (const float*)d_in[19],
                       (const float*)d_in[20], (const float*)d_in[21],
                       (float*)d_out);
}

// round 11
// speedup vs baseline: 1.0087x; 1.0000x over previous
#include <cuda_runtime.h>
#include <math.h>

#define NN_  262144
#define B_   256
#define N_   1024
#define DEG_ 8
#define E_   (NN_*DEG_)
#define D_   128

typedef unsigned long long ull;

// ------------------------- scratch -------------------------
__device__ float g_X[NN_*D_];
__device__ float g_AGG[NN_*D_];
__device__ float g_score[NN_];
__device__ float g_gate[NN_];
__device__ int   g_nm[NN_];
__device__ int   g_off[NN_];
__device__ int   g_deg[NN_];
__device__ int   g_csr[E_];
__device__ int   g_rows[2][NN_];   // kept-row lists (ping-pong)
__device__ float g_H[B_*2*D_];

// ------------------------- f32x2 helpers -------------------------
__device__ __forceinline__ ull bcast2(float a){ ull r; asm("mov.b64 %0, {%1,%1};" : "=l"(r) : "f"(a)); return r; }
__device__ __forceinline__ float2 unpk(ull v){ float2 f; asm("mov.b64 {%0,%1}, %2;" : "=f"(f.x),"=f"(f.y) : "l"(v)); return f; }
__device__ __forceinline__ void fma2(ull &d, ull a, ull b){ asm("fma.rn.f32x2 %0, %1, %2, %0;" : "+l"(d) : "l"(a),"l"(b)); }

// ------------------------- init -------------------------
__global__ void k_init(const int* __restrict__ ids, const float* __restrict__ emb){
    long tid0 = (long)blockIdx.x*blockDim.x + threadIdx.x;
    long stride = (long)gridDim.x*blockDim.x;
    const float4* emb4 = (const float4*)emb;
    float4* X4 = (float4*)g_X;
    for (long v = tid0; v < (long)NN_*32; v += stride){
        int n = (int)(v >> 5), c = (int)(v & 31);
        int id = ids[n];
        X4[v] = emb4[(long)id*32 + c];
    }
    for (long i = tid0; i < NN_; i += stride) g_nm[i] = 1;
    for (long i = tid0; i < B_*2*D_; i += stride) g_H[i] = 0.f;
}

// ------------------------- CSR build: one kernel, per-graph in shared -------------------------
__global__ void __launch_bounds__(1024) k_csr(const int* __restrict__ ei){
    __shared__ int scnt[1024];
    __shared__ int soff[1024];
    int b = blockIdx.x, t = threadIdx.x;
    scnt[t] = 0;
    __syncthreads();
    int ebase = b * (N_*DEG_);
    int dl[8];
    #pragma unroll
    for (int i = 0; i < 8; i++){
        dl[i] = ei[E_ + ebase + t + i*1024] - b*N_;
        atomicAdd(&scnt[dl[i]], 1);
    }
    __syncthreads();
    int d = scnt[t];
    soff[t] = d;
    __syncthreads();
    for (int o = 1; o < 1024; o <<= 1){
        int v = (t >= o) ? soff[t-o] : 0;
        __syncthreads();
        soff[t] += v;
        __syncthreads();
    }
    int excl = soff[t] - d;
    g_off[b*N_ + t] = ebase + excl;
    g_deg[b*N_ + t] = d;
    __syncthreads();
    scnt[t] = excl;          // reuse as fill cursor
    __syncthreads();
    #pragma unroll
    for (int i = 0; i < 8; i++){
        int pos = atomicAdd(&scnt[dl[i]], 1);
        g_csr[ebase + pos] = ei[ebase + t + i*1024];
    }
}

// ------------------------- mean aggregation (gather, kept rows only) -------------------------
// Dropped-source rows of X are exactly zero, so the sum needs no mask; only the
// count does. Source indices prefetched 8 at a time -> MLP ~8.
__global__ void __launch_bounds__(256) k_agg(int sel, int prevK){
    int w = (blockIdx.x*256 + threadIdx.x) >> 5;
    int lane = threadIdx.x & 31;
    int g;
    if (sel < 0) g = w;
    else { int b = w / prevK; g = g_rows[sel][b*N_ + (w - b*prevK)]; }
    float4 acc = make_float4(0.f,0.f,0.f,0.f);
    int cnt = 0;
    int off = g_off[g], dcnt = g_deg[g];
    const float4* X4 = (const float4*)g_X;
    for (int base = 0; base < dcnt; base += 8){
        int m = dcnt - base; if (m > 8) m = 8;
        int ss[8];
        #pragma unroll
        for (int j = 0; j < 8; j++) ss[j] = (j < m) ? g_csr[off + base + j] : 0;
        #pragma unroll
        for (int j = 0; j < 8; j++) if (j < m){
            float4 v = X4[(long)ss[j]*32 + lane];
            acc.x += v.x; acc.y += v.y; acc.z += v.z; acc.w += v.w;
            cnt += g_nm[ss[j]];
        }
    }
    float inv = 1.0f / (float)(cnt > 1 ? cnt : 1);
    acc.x *= inv; acc.y *= inv; acc.z *= inv; acc.w *= inv;
    ((float4*)g_AGG)[(long)g*32 + lane] = acc;
}

// ------------------------- fused GEMM + score -------------------------
// X[g] = relu(AGG[g]@Wl + bl + X[g]@Wr) for kept rows g; score[g] = X[g].p
// Block: 128 thr = 4 warps x 32 rows (row-pairs packed in f32x2 accumulators).
// Shared holds A,X transposed [k][r] with an even-XOR swizzle (conflict-free
// stores, broadcast reads, row-pairs stay adjacent).
#define SWA(k, r) (((k)<<5) + ((r) ^ ((k)&30)))

__global__ void __launch_bounds__(128) k_gemm(const float* __restrict__ Wl,
                                              const float* __restrict__ blp,
                                              const float* __restrict__ Wr,
                                              const float* __restrict__ p,
                                              int sel, int prevK){
    __shared__ float sA[128*32];
    __shared__ float sXm[128*32];
    __shared__ int sRow[32];
    int t = threadIdx.x;
    int rb = blockIdx.x * 32;
    if (t < 32){
        int j = rb + t, g;
        if (sel < 0) g = j;
        else { int b = j / prevK; g = g_rows[sel][b*N_ + (j - b*prevK)]; }
        sRow[t] = g;
    }
    __syncthreads();
    {   // load + transpose: warp w -> rows 8w..8w+7; lane = (rquad, c8)
        int w = t >> 5, lane = t & 31;
        int rq = lane >> 3, c8 = lane & 7;
        const float4* A4 = (const float4*)g_AGG;
        const float4* X4 = (const float4*)g_X;
        #pragma unroll
        for (int half = 0; half < 2; half++){
            int r = w*8 + half*4 + rq;
            long gr = (long)sRow[r]*32;
            #pragma unroll
            for (int cg = 0; cg < 4; cg++){
                int ch = c8 + cg*8;
                float4 a = A4[gr + ch];
                float4 x = X4[gr + ch];
                int k0 = ch*4;
                sA [SWA(k0+0,r)] = a.x; sA [SWA(k0+1,r)] = a.y;
                sA [SWA(k0+2,r)] = a.z; sA [SWA(k0+3,r)] = a.w;
                sXm[SWA(k0+0,r)] = x.x; sXm[SWA(k0+1,r)] = x.y;
                sXm[SWA(k0+2,r)] = x.z; sXm[SWA(k0+3,r)] = x.w;
            }
        }
    }
    __syncthreads();

    int q = t & 31, h = t >> 5;
    int r0 = h * 8;
    const float4* Wl4 = (const float4*)Wl;
    const float4* Wr4 = (const float4*)Wr;
    float4 bl4 = ((const float4*)blp)[q];
    ull acc[4][4];
    {
        ull b0 = bcast2(bl4.x), b1 = bcast2(bl4.y), b2 = bcast2(bl4.z), b3 = bcast2(bl4.w);
        #pragma unroll
        for (int rr = 0; rr < 4; rr++){ acc[rr][0]=b0; acc[rr][1]=b1; acc[rr][2]=b2; acc[rr][3]=b3; }
    }

    #pragma unroll 2
    for (int k = 0; k < 128; k++){
        float4 wl = Wl4[k*32 + q];
        float4 wr = Wr4[k*32 + q];
        ull wl0=bcast2(wl.x), wl1=bcast2(wl.y), wl2=bcast2(wl.z), wl3=bcast2(wl.w);
        ull wr0=bcast2(wr.x), wr1=bcast2(wr.y), wr2=bcast2(wr.z), wr3=bcast2(wr.w);
        #pragma unroll
        for (int rr = 0; rr < 4; rr++){
            ull a2 = *(const ull*)&sA [SWA(k, r0 + 2*rr)];
            ull x2 = *(const ull*)&sXm[SWA(k, r0 + 2*rr)];
            fma2(acc[rr][0], a2, wl0); fma2(acc[rr][0], x2, wr0);
            fma2(acc[rr][1], a2, wl1); fma2(acc[rr][1], x2, wr1);
            fma2(acc[rr][2], a2, wl2); fma2(acc[rr][2], x2, wr2);
            fma2(acc[rr][3], a2, wl3); fma2(acc[rr][3], x2, wr3);
        }
    }

    float4 p4 = ((const float4*)p)[q];
    float4* Xo = (float4*)g_X;
    #pragma unroll
    for (int rr = 0; rr < 4; rr++){
        float2 c0 = unpk(acc[rr][0]), c1 = unpk(acc[rr][1]);
        float2 c2 = unpk(acc[rr][2]), c3 = unpk(acc[rr][3]);
        float4 o0 = make_float4(fmaxf(c0.x,0.f), fmaxf(c1.x,0.f), fmaxf(c2.x,0.f), fmaxf(c3.x,0.f));
        float4 o1 = make_float4(fmaxf(c0.y,0.f), fmaxf(c1.y,0.f), fmaxf(c2.y,0.f), fmaxf(c3.y,0.f));
        int ga = sRow[r0 + 2*rr], gb = sRow[r0 + 2*rr + 1];
        Xo[(long)ga*32 + q] = o0;
        Xo[(long)gb*32 + q] = o1;
        float s0 = o0.x*p4.x + o0.y*p4.y + o0.z*p4.z + o0.w*p4.w;
        float s1 = o1.x*p4.x + o1.y*p4.y + o1.z*p4.z + o1.w*p4.w;
        #pragma unroll
        for (int o = 16; o > 0; o >>= 1){
            s0 += __shfl_xor_sync(0xffffffffu, s0, o);
            s1 += __shfl_xor_sync(0xffffffffu, s1, o);
        }
        if (q == 0){ g_score[ga] = s0; g_score[gb] = s1; }
    }
}

// ------------------------- per-graph topk (sort-only; scores precomputed) -------------------------
__device__ __forceinline__ unsigned ordu(float f){
    unsigned u = __float_as_uint(f);
    return (u >> 31) ? ~u : (u | 0x80000000u);
}

__global__ void __launch_bounds__(1024) k_topk(const float* __restrict__ p, int K, int buf){
    __shared__ float sp[128];
    __shared__ ull skey[1024];
    __shared__ int skeep[1024];
    __shared__ float snorm;
    int b = blockIdx.x, t = threadIdx.x;
    if (t < 128) sp[t] = p[t];
    __syncthreads();
    if (t == 0){
        float s = 0.f;
        for (int i = 0; i < 128; i++) s += sp[i]*sp[i];
        snorm = rsqrtf(s);
    }
    __syncthreads();
    int g = b*N_ + t;
    int oldnm = g_nm[g];
    float sc = g_score[g] * snorm;
    float skk = oldnm ? sc : -INFINITY;
    skey[t] = (((ull)(~ordu(skk))) << 32) | (unsigned)t;
    skeep[t] = 0;

    for (unsigned kk = 2; kk <= 1024; kk <<= 1){
        for (unsigned j = kk >> 1; j > 0; j >>= 1){
            __syncthreads();
            unsigned ixj = t ^ j;
            if (ixj > (unsigned)t){
                ull a = skey[t], bb = skey[ixj];
                bool asc = ((t & kk) == 0);
                bool sw = asc ? (a > bb) : (a < bb);
                if (sw){ skey[t] = bb; skey[ixj] = a; }
            }
        }
    }
    __syncthreads();
    if (t < K){
        int idx = (int)(skey[t] & 0xffffffffu);
        skeep[idx] = 1;
        g_rows[buf][b*N_ + t] = b*N_ + idx;
    }
    __syncthreads();
    int keep = skeep[t];
    g_nm[g] = keep;
    g_gate[g] = keep ? tanhf(sc) : 0.f;
}

// ------------------------- fused scale + readout (prev-kept rows only) -------------------------
__global__ void __launch_bounds__(512) k_sr(int sel, int prevK, float Kinv){
    __shared__ float4 ssum[16][32];
    __shared__ float4 smax[16][32];
    int b = blockIdx.x, t = threadIdx.x;
    int grp = t >> 5, lane = t & 31;
    float4 sum = make_float4(0.f,0.f,0.f,0.f);
    float4 mx  = make_float4(-INFINITY,-INFINITY,-INFINITY,-INFINITY);
    float4* X4 = (float4*)g_X;
    for (int j = grp; j < prevK; j += 16){
        int g = (sel < 0) ? b*N_ + j : g_rows[sel][b*N_ + j];
        float gt = g_gate[g];
        float4 v = X4[(long)g*32 + lane];
        v.x *= gt; v.y *= gt; v.z *= gt; v.w *= gt;
        X4[(long)g*32 + lane] = v;
        if (g_nm[g]){
            sum.x += v.x; sum.y += v.y; sum.z += v.z; sum.w += v.w;
            mx.x = fmaxf(mx.x, v.x); mx.y = fmaxf(mx.y, v.y);
            mx.z = fmaxf(mx.z, v.z); mx.w = fmaxf(mx.w, v.w);
        }
    }
    ssum[grp][lane] = sum; smax[grp][lane] = mx;
    __syncthreads();
    if (t < 32){
        float4 S = make_float4(0.f,0.f,0.f,0.f);
        float4 M = make_float4(-INFINITY,-INFINITY,-INFINITY,-INFINITY);
        #pragma unroll
        for (int gg = 0; gg < 16; gg++){
            float4 s = ssum[gg][t], m = smax[gg][t];
            S.x += s.x; S.y += s.y; S.z += s.z; S.w += s.w;
            M.x = fmaxf(M.x, m.x); M.y = fmaxf(M.y, m.y);
            M.z = fmaxf(M.z, m.z); M.w = fmaxf(M.w, m.w);
        }
        g_H[b*256 + 4*t+0] += M.x; g_H[b*256 + 4*t+1] += M.y;
        g_H[b*256 + 4*t+2] += M.z; g_H[b*256 + 4*t+3] += M.w;
        g_H[b*256 + 128 + 4*t+0] += S.x*Kinv; g_H[b*256 + 128 + 4*t+1] += S.y*Kinv;
        g_H[b*256 + 128 + 4*t+2] += S.z*Kinv; g_H[b*256 + 128 + 4*t+3] += S.w*Kinv;
    }
}

// ------------------------- final MLP -------------------------
__global__ void __launch_bounds__(128) k_mlp(const float* __restrict__ W1, const float* __restrict__ b1,
                                             const float* __restrict__ W2, const float* __restrict__ b2,
                                             const float* __restrict__ W3, const float* __restrict__ b3,
                                             float* __restrict__ out){
    __shared__ float h[256], h1[128], h2[64];
    int b = blockIdx.x, t = threadIdx.x;
    h[t] = g_H[b*256 + t];
    h[t + 128] = g_H[b*256 + 128 + t];
    __syncthreads();
    float a = b1[t];
    #pragma unroll 8
    for (int k = 0; k < 256; k++) a += h[k] * W1[k*128 + t];
    h1[t] = fmaxf(a, 0.f);
    __syncthreads();
    if (t < 64){
        float a2 = b2[t];
        #pragma unroll 8
        for (int k = 0; k < 128; k++) a2 += h1[k] * W2[k*64 + t];
        h2[t] = fmaxf(a2, 0.f);
    }
    __syncthreads();
    if (t == 0){
        float z = b3[0];
        for (int k = 0; k < 64; k++) z += h2[k] * W3[k];
        out[b] = 1.f / (1.f + expf(-z));
    }
}

// ------------------------- launch -------------------------
extern "C" void kernel_launch(void* const* d_in, const int* in_sizes, int n_in,
                              void* d_out, int out_size){
    const int*   x_ids = (const int*)d_in[0];
    const int*   ei    = (const int*)d_in[1];
    const float* emb   = (const float*)d_in[3];
    const float* Wl[3] = {(const float*)d_in[4],  (const float*)d_in[8],  (const float*)d_in[12]};
    const float* bl[3] = {(const float*)d_in[5],  (const float*)d_in[9],  (const float*)d_in[13]};
    const float* Wr[3] = {(const float*)d_in[6],  (const float*)d_in[10], (const float*)d_in[14]};
    const float* pp[3] = {(const float*)d_in[7],  (const float*)d_in[11], (const float*)d_in[15]};
    const int pk[3] = {1024, 820, 656};   // rows alive entering layer l (per graph)
    const int Ks[3] = {820, 656, 525};    // rows kept by layer l's topk

    k_init<<<8192, 256>>>(x_ids, emb);
    k_csr<<<B_, 1024>>>(ei);

    for (int l = 0; l < 3; l++){
        int sel = (l == 0) ? -1 : ((l-1) & 1);
        k_agg <<<32*pk[l], 256>>>(sel, pk[l]);
        k_gemm<<<8*pk[l], 128>>>(Wl[l], bl[l], Wr[l], pp[l], sel, pk[l]);
        k_topk<<<B_, 1024>>>(pp[l], Ks[l], l & 1);
        k_sr  <<<B_, 512>>>(sel, pk[l], 1.0f / (float)Ks[l]);
    }
    k_mlp<<<B_, 128>>>((const float*)d_in[16], (const float*)d_in[17],
                       (const float*)d_in[18], (const float*)d_in[19],
                       (const float*)d_in[20], (const float*)d_in[21],
                       (float*)d_out);
}

// round 12
// speedup vs baseline: 1.0103x; 1.0016x over previous
#include <cuda_runtime.h>
#include <math.h>

#define NN_  262144
#define B_   256
#define N_   1024
#define DEG_ 8
#define E_   (NN_*DEG_)
#define D_   128

typedef unsigned long long ull;

// ------------------------- scratch -------------------------
__device__ float g_X[NN_*D_];
__device__ float g_AGG[NN_*D_];
__device__ float g_score[NN_];
__device__ float g_gate[NN_];
__device__ int   g_nm[NN_];
__device__ int   g_off[NN_];
__device__ int   g_deg[NN_];
__device__ int   g_csr[E_];
__device__ int   g_rows[2][NN_];   // kept-row lists (ping-pong)
__device__ float g_H[B_*2*D_];

// ------------------------- f32x2 helpers -------------------------
__device__ __forceinline__ ull bcast2(float a){ ull r; asm("mov.b64 %0, {%1,%1};" : "=l"(r) : "f"(a)); return r; }
__device__ __forceinline__ float2 unpk(ull v){ float2 f; asm("mov.b64 {%0,%1}, %2;" : "=f"(f.x),"=f"(f.y) : "l"(v)); return f; }
__device__ __forceinline__ void fma2(ull &d, ull a, ull b){ asm("fma.rn.f32x2 %0, %1, %2, %0;" : "+l"(d) : "l"(a),"l"(b)); }

// ------------------------- init -------------------------
__global__ void k_init(const int* __restrict__ ids, const float* __restrict__ emb){
    long tid0 = (long)blockIdx.x*blockDim.x + threadIdx.x;
    long stride = (long)gridDim.x*blockDim.x;
    const float4* emb4 = (const float4*)emb;
    float4* X4 = (float4*)g_X;
    for (long v = tid0; v < (long)NN_*32; v += stride){
        int n = (int)(v >> 5), c = (int)(v & 31);
        int id = ids[n];
        X4[v] = emb4[(long)id*32 + c];
    }
    for (long i = tid0; i < NN_; i += stride) g_nm[i] = 1;
    for (long i = tid0; i < B_*2*D_; i += stride) g_H[i] = 0.f;
}

// ------------------------- CSR build: one kernel, per-graph in shared -------------------------
__global__ void __launch_bounds__(1024) k_csr(const int* __restrict__ ei){
    __shared__ int scnt[1024];
    __shared__ int soff[1024];
    int b = blockIdx.x, t = threadIdx.x;
    scnt[t] = 0;
    __syncthreads();
    int ebase = b * (N_*DEG_);
    int dl[8];
    #pragma unroll
    for (int i = 0; i < 8; i++){
        dl[i] = ei[E_ + ebase + t + i*1024] - b*N_;
        atomicAdd(&scnt[dl[i]], 1);
    }
    __syncthreads();
    int d = scnt[t];
    soff[t] = d;
    __syncthreads();
    for (int o = 1; o < 1024; o <<= 1){
        int v = (t >= o) ? soff[t-o] : 0;
        __syncthreads();
        soff[t] += v;
        __syncthreads();
    }
    int excl = soff[t] - d;
    g_off[b*N_ + t] = ebase + excl;
    g_deg[b*N_ + t] = d;
    __syncthreads();
    scnt[t] = excl;          // reuse as fill cursor
    __syncthreads();
    #pragma unroll
    for (int i = 0; i < 8; i++){
        int pos = atomicAdd(&scnt[dl[i]], 1);
        g_csr[ebase + pos] = ei[ebase + t + i*1024];
    }
}

// ------------------------- mean aggregation (gather, kept rows only) -------------------------
// Dropped-source rows of X are exactly zero, so the sum needs no mask; only the
// count does. Source indices prefetched 8 at a time -> MLP ~8.
__global__ void __launch_bounds__(256) k_agg(int sel, int prevK){
    int w = (blockIdx.x*256 + threadIdx.x) >> 5;
    int lane = threadIdx.x & 31;
    int g;
    if (sel < 0) g = w;
    else { int b = w / prevK; g = g_rows[sel][b*N_ + (w - b*prevK)]; }
    float4 acc = make_float4(0.f,0.f,0.f,0.f);
    int cnt = 0;
    int off = g_off[g], dcnt = g_deg[g];
    const float4* X4 = (const float4*)g_X;
    for (int base = 0; base < dcnt; base += 8){
        int m = dcnt - base; if (m > 8) m = 8;
        int ss[8];
        #pragma unroll
        for (int j = 0; j < 8; j++) ss[j] = (j < m) ? g_csr[off + base + j] : 0;
        #pragma unroll
        for (int j = 0; j < 8; j++) if (j < m){
            float4 v = X4[(long)ss[j]*32 + lane];
            acc.x += v.x; acc.y += v.y; acc.z += v.z; acc.w += v.w;
            cnt += g_nm[ss[j]];
        }
    }
    float inv = 1.0f / (float)(cnt > 1 ? cnt : 1);
    acc.x *= inv; acc.y *= inv; acc.z *= inv; acc.w *= inv;
    ((float4*)g_AGG)[(long)g*32 + lane] = acc;
}

// ------------------------- fused GEMM + score -------------------------
// X[g] = relu(AGG[g]@Wl + bl + X[g]@Wr) for kept rows g; score[g] = X[g].p
// Block: 128 thr = 4 warps x 32 rows (row-pairs packed in f32x2 accumulators).
// Shared holds A,X transposed [k][r] with an even-XOR swizzle (conflict-free
// stores, broadcast reads, row-pairs stay adjacent).
#define SWA(k, r) (((k)<<5) + ((r) ^ ((k)&30)))

__global__ void __launch_bounds__(128) k_gemm(const float* __restrict__ Wl,
                                              const float* __restrict__ blp,
                                              const float* __restrict__ Wr,
                                              const float* __restrict__ p,
                                              int sel, int prevK){
    __shared__ float sA[128*32];
    __shared__ float sXm[128*32];
    __shared__ int sRow[32];
    int t = threadIdx.x;
    int rb = blockIdx.x * 32;
    if (t < 32){
        int j = rb + t, g;
        if (sel < 0) g = j;
        else { int b = j / prevK; g = g_rows[sel][b*N_ + (j - b*prevK)]; }
        sRow[t] = g;
    }
    __syncthreads();
    {   // load + transpose: warp w -> rows 8w..8w+7; lane = (rquad, c8)
        int w = t >> 5, lane = t & 31;
        int rq = lane >> 3, c8 = lane & 7;
        const float4* A4 = (const float4*)g_AGG;
        const float4* X4 = (const float4*)g_X;
        #pragma unroll
        for (int half = 0; half < 2; half++){
            int r = w*8 + half*4 + rq;
            long gr = (long)sRow[r]*32;
            #pragma unroll
            for (int cg = 0; cg < 4; cg++){
                int ch = c8 + cg*8;
                float4 a = A4[gr + ch];
                float4 x = X4[gr + ch];
                int k0 = ch*4;
                sA [SWA(k0+0,r)] = a.x; sA [SWA(k0+1,r)] = a.y;
                sA [SWA(k0+2,r)] = a.z; sA [SWA(k0+3,r)] = a.w;
                sXm[SWA(k0+0,r)] = x.x; sXm[SWA(k0+1,r)] = x.y;
                sXm[SWA(k0+2,r)] = x.z; sXm[SWA(k0+3,r)] = x.w;
            }
        }
    }
    __syncthreads();

    int q = t & 31, h = t >> 5;
    int r0 = h * 8;
    const float4* Wl4 = (const float4*)Wl;
    const float4* Wr4 = (const float4*)Wr;
    float4 bl4 = ((const float4*)blp)[q];
    ull acc[4][4];
    {
        ull b0 = bcast2(bl4.x), b1 = bcast2(bl4.y), b2 = bcast2(bl4.z), b3 = bcast2(bl4.w);
        #pragma unroll
        for (int rr = 0; rr < 4; rr++){ acc[rr][0]=b0; acc[rr][1]=b1; acc[rr][2]=b2; acc[rr][3]=b3; }
    }

    #pragma unroll 2
    for (int k = 0; k < 128; k++){
        float4 wl = Wl4[k*32 + q];
        float4 wr = Wr4[k*32 + q];
        ull wl0=bcast2(wl.x), wl1=bcast2(wl.y), wl2=bcast2(wl.z), wl3=bcast2(wl.w);
        ull wr0=bcast2(wr.x), wr1=bcast2(wr.y), wr2=bcast2(wr.z), wr3=bcast2(wr.w);
        #pragma unroll
        for (int rr = 0; rr < 4; rr++){
            ull a2 = *(const ull*)&sA [SWA(k, r0 + 2*rr)];
            ull x2 = *(const ull*)&sXm[SWA(k, r0 + 2*rr)];
            fma2(acc[rr][0], a2, wl0); fma2(acc[rr][0], x2, wr0);
            fma2(acc[rr][1], a2, wl1); fma2(acc[rr][1], x2, wr1);
            fma2(acc[rr][2], a2, wl2); fma2(acc[rr][2], x2, wr2);
            fma2(acc[rr][3], a2, wl3); fma2(acc[rr][3], x2, wr3);
        }
    }

    float4 p4 = ((const float4*)p)[q];
    float4* Xo = (float4*)g_X;
    #pragma unroll
    for (int rr = 0; rr < 4; rr++){
        float2 c0 = unpk(acc[rr][0]), c1 = unpk(acc[rr][1]);
        float2 c2 = unpk(acc[rr][2]), c3 = unpk(acc[rr][3]);
        float4 o0 = make_float4(fmaxf(c0.x,0.f), fmaxf(c1.x,0.f), fmaxf(c2.x,0.f), fmaxf(c3.x,0.f));
        float4 o1 = make_float4(fmaxf(c0.y,0.f), fmaxf(c1.y,0.f), fmaxf(c2.y,0.f), fmaxf(c3.y,0.f));
        int ga = sRow[r0 + 2*rr], gb = sRow[r0 + 2*rr + 1];
        Xo[(long)ga*32 + q] = o0;
        Xo[(long)gb*32 + q] = o1;
        float s0 = o0.x*p4.x + o0.y*p4.y + o0.z*p4.z + o0.w*p4.w;
        float s1 = o1.x*p4.x + o1.y*p4.y + o1.z*p4.z + o1.w*p4.w;
        #pragma unroll
        for (int o = 16; o > 0; o >>= 1){
            s0 += __shfl_xor_sync(0xffffffffu, s0, o);
            s1 += __shfl_xor_sync(0xffffffffu, s1, o);
        }
        if (q == 0){ g_score[ga] = s0; g_score[gb] = s1; }
    }
}

// ------------------------- per-graph topk (sort-only; scores precomputed) -------------------------
__device__ __forceinline__ unsigned ordu(float f){
    unsigned u = __float_as_uint(f);
    return (u >> 31) ? ~u : (u | 0x80000000u);
}

__global__ void __launch_bounds__(1024) k_topk(const float* __restrict__ p, int K, int buf){
    __shared__ float sp[128];
    __shared__ ull skey[1024];
    __shared__ int skeep[1024];
    __shared__ float snorm;
    int b = blockIdx.x, t = threadIdx.x;
    if (t < 128) sp[t] = p[t];
    __syncthreads();
    if (t == 0){
        float s = 0.f;
        for (int i = 0; i < 128; i++) s += sp[i]*sp[i];
        snorm = rsqrtf(s);
    }
    __syncthreads();
    int g = b*N_ + t;
    int oldnm = g_nm[g];
    float sc = g_score[g] * snorm;
    float skk = oldnm ? sc : -INFINITY;
    skey[t] = (((ull)(~ordu(skk))) << 32) | (unsigned)t;
    skeep[t] = 0;

    for (unsigned kk = 2; kk <= 1024; kk <<= 1){
        for (unsigned j = kk >> 1; j > 0; j >>= 1){
            __syncthreads();
            unsigned ixj = t ^ j;
            if (ixj > (unsigned)t){
                ull a = skey[t], bb = skey[ixj];
                bool asc = ((t & kk) == 0);
                bool sw = asc ? (a > bb) : (a < bb);
                if (sw){ skey[t] = bb; skey[ixj] = a; }
            }
        }
    }
    __syncthreads();
    if (t < K){
        int idx = (int)(skey[t] & 0xffffffffu);
        skeep[idx] = 1;
        g_rows[buf][b*N_ + t] = b*N_ + idx;
    }
    __syncthreads();
    int keep = skeep[t];
    g_nm[g] = keep;
    g_gate[g] = keep ? tanhf(sc) : 0.f;
}

// ------------------------- fused scale + readout (prev-kept rows only) -------------------------
__global__ void __launch_bounds__(512) k_sr(int sel, int prevK, float Kinv){
    __shared__ float4 ssum[16][32];
    __shared__ float4 smax[16][32];
    int b = blockIdx.x, t = threadIdx.x;
    int grp = t >> 5, lane = t & 31;
    float4 sum = make_float4(0.f,0.f,0.f,0.f);
    float4 mx  = make_float4(-INFINITY,-INFINITY,-INFINITY,-INFINITY);
    float4* X4 = (float4*)g_X;
    for (int j = grp; j < prevK; j += 16){
        int g = (sel < 0) ? b*N_ + j : g_rows[sel][b*N_ + j];
        float gt = g_gate[g];
        float4 v = X4[(long)g*32 + lane];
        v.x *= gt; v.y *= gt; v.z *= gt; v.w *= gt;
        X4[(long)g*32 + lane] = v;
        if (g_nm[g]){
            sum.x += v.x; sum.y += v.y; sum.z += v.z; sum.w += v.w;
            mx.x = fmaxf(mx.x, v.x); mx.y = fmaxf(mx.y, v.y);
            mx.z = fmaxf(mx.z, v.z); mx.w = fmaxf(mx.w, v.w);
        }
    }
    ssum[grp][lane] = sum; smax[grp][lane] = mx;
    __syncthreads();
    if (t < 32){
        float4 S = make_float4(0.f,0.f,0.f,0.f);
        float4 M = make_float4(-INFINITY,-INFINITY,-INFINITY,-INFINITY);
        #pragma unroll
        for (int gg = 0; gg < 16; gg++){
            float4 s = ssum[gg][t], m = smax[gg][t];
            S.x += s.x; S.y += s.y; S.z += s.z; S.w += s.w;
            M.x = fmaxf(M.x, m.x); M.y = fmaxf(M.y, m.y);
            M.z = fmaxf(M.z, m.z); M.w = fmaxf(M.w, m.w);
        }
        g_H[b*256 + 4*t+0] += M.x; g_H[b*256 + 4*t+1] += M.y;
        g_H[b*256 + 4*t+2] += M.z; g_H[b*256 + 4*t+3] += M.w;
        g_H[b*256 + 128 + 4*t+0] += S.x*Kinv; g_H[b*256 + 128 + 4*t+1] += S.y*Kinv;
        g_H[b*256 + 128 + 4*t+2] += S.z*Kinv; g_H[b*256 + 128 + 4*t+3] += S.w*Kinv;
    }
}

// ------------------------- final MLP -------------------------
__global__ void __launch_bounds__(128) k_mlp(const float* __restrict__ W1, const float* __restrict__ b1,
                                             const float* __restrict__ W2, const float* __restrict__ b2,
                                             const float* __restrict__ W3, const float* __restrict__ b3,
                                             float* __restrict__ out){
    __shared__ float h[256], h1[128], h2[64];
    int b = blockIdx.x, t = threadIdx.x;
    h[t] = g_H[b*256 + t];
    h[t + 128] = g_H[b*256 + 128 + t];
    __syncthreads();
    float a = b1[t];
    #pragma unroll 8
    for (int k = 0; k < 256; k++) a += h[k] * W1[k*128 + t];
    h1[t] = fmaxf(a, 0.f);
    __syncthreads();
    if (t < 64){
        float a2 = b2[t];
        #pragma unroll 8
        for (int k = 0; k < 128; k++) a2 += h1[k] * W2[k*64 + t];
        h2[t] = fmaxf(a2, 0.f);
    }
    __syncthreads();
    if (t == 0){
        float z = b3[0];
        for (int k = 0; k < 64; k++) z += h2[k] * W3[k];
        out[b] = 1.f / (1.f + expf(-z));
    }
}

// ------------------------- launch -------------------------
extern "C" void kernel_launch(void* const* d_in, const int* in_sizes, int n_in,
                              void* d_out, int out_size){
    const int*   x_ids = (const int*)d_in[0];
    const int*   ei    = (const int*)d_in[1];
    const float* emb   = (const float*)d_in[3];
    const float* Wl[3] = {(const float*)d_in[4],  (const float*)d_in[8],  (const float*)d_in[12]};
    const float* bl[3] = {(const float*)d_in[5],  (const float*)d_in[9],  (const float*)d_in[13]};
    const float* Wr[3] = {(const float*)d_in[6],  (const float*)d_in[10], (const float*)d_in[14]};
    const float* pp[3] = {(const float*)d_in[7],  (const float*)d_in[11], (const float*)d_in[15]};
    const int pk[3] = {1024, 820, 656};   // rows alive entering layer l (per graph)
    const int Ks[3] = {820, 656, 525};    // rows kept by layer l's topk

    k_init<<<8192, 256>>>(x_ids, emb);
    k_csr<<<B_, 1024>>>(ei);

    for (int l = 0; l < 3; l++){
        int sel = (l == 0) ? -1 : ((l-1) & 1);
        k_agg <<<32*pk[l], 256>>>(sel, pk[l]);
        k_gemm<<<8*pk[l], 128>>>(Wl[l], bl[l], Wr[l], pp[l], sel, pk[l]);
        k_topk<<<B_, 1024>>>(pp[l], Ks[l], l & 1);
        k_sr  <<<B_, 512>>>(sel, pk[l], 1.0f / (float)Ks[l]);
    }
    k_mlp<<<B_, 128>>>((const float*)d_in[16], (const float*)d_in[17],
                       (const float*)d_in[18], (const float*)d_in[19],
                       (const float*)d_in[20], (const float*)d_in[21],
                       (float*)d_out);
}